// round 4
// baseline (speedup 1.0000x reference)
#include <cuda_runtime.h>
#include <cuda_bf16.h>

// Problem constants
#define T   2048
#define D   2048
#define NH  16
#define DH  128
#define DRH 64
#define DC  512
#define QKD 192   // DH + DRH

// -------- scratch (device globals; no allocation allowed) --------
__device__ float g_ckv[(size_t)T * DC];
__device__ float g_cq [(size_t)T * DC];
__device__ float g_q  [(size_t)NH * T * QKD];
__device__ float g_k  [(size_t)NH * T * QKD];
__device__ float g_v  [(size_t)NH * T * DH];
__device__ float g_kr [(size_t)T * DRH];
__device__ float g_logits[(size_t)NH * T * T];
__device__ float g_attn[(size_t)T * NH * DH];
__device__ float g_wot [(size_t)D * NH * DH];

typedef unsigned long long ull;

__device__ __forceinline__ void ffma2(ull& d, ull a, ull b) {
    asm("fma.rn.f32x2 %0, %1, %2, %0;" : "+l"(d) : "l"(a), "l"(b));
}
__device__ __forceinline__ ull dup2(float x) {
    ull r;
    asm("mov.b64 %0, {%1, %1};" : "=l"(r) : "f"(x));
    return r;
}
union F2u { ull u; float2 f; };

#define BM 128
#define BN 128
#define BK 16
#define PAD 4

// ============================================================
// NT body: C[m,n] = sum_k A[m,k]*B[n,k], double-buffered smem
// ============================================================
__device__ __forceinline__ void nt128_body(
    const float* __restrict__ A, const float* __restrict__ B, float* __restrict__ C,
    int K, int lda, int ldb, int ldc, int bm, int bn)
{
    __shared__ float As[2][BK][BM + PAD];
    __shared__ float Bs[2][BK][BN + PAD];
    const int tid = threadIdx.x;
    const int tx = tid & 15;
    const int ty = tid >> 4;
    const int arow = tid >> 2;
    const int acol = (tid & 3) * 4;

    const float* Ap0 = A + (long long)(bm + arow)      * lda + acol;
    const float* Ap1 = A + (long long)(bm + arow + 64) * lda + acol;
    const float* Bp0 = B + (long long)(bn + arow)      * ldb + acol;
    const float* Bp1 = B + (long long)(bn + arow + 64) * ldb + acol;

    float4 a0 = *(const float4*)Ap0;
    float4 a1 = *(const float4*)Ap1;
    float4 b0 = *(const float4*)Bp0;
    float4 b1 = *(const float4*)Bp1;

    ull acc2[4][8] = {};
    const int nt = K / BK;
    int buf = 0;

    As[0][acol + 0][arow] = a0.x; As[0][acol + 1][arow] = a0.y;
    As[0][acol + 2][arow] = a0.z; As[0][acol + 3][arow] = a0.w;
    As[0][acol + 0][arow + 64] = a1.x; As[0][acol + 1][arow + 64] = a1.y;
    As[0][acol + 2][arow + 64] = a1.z; As[0][acol + 3][arow + 64] = a1.w;
    Bs[0][acol + 0][arow] = b0.x; Bs[0][acol + 1][arow] = b0.y;
    Bs[0][acol + 2][arow] = b0.z; Bs[0][acol + 3][arow] = b0.w;
    Bs[0][acol + 0][arow + 64] = b1.x; Bs[0][acol + 1][arow + 64] = b1.y;
    Bs[0][acol + 2][arow + 64] = b1.z; Bs[0][acol + 3][arow + 64] = b1.w;
    __syncthreads();

    for (int it = 0; it < nt; ++it) {
        if (it + 1 < nt) {
            const int off = (it + 1) * BK;
            a0 = *(const float4*)(Ap0 + off);
            a1 = *(const float4*)(Ap1 + off);
            b0 = *(const float4*)(Bp0 + off);
            b1 = *(const float4*)(Bp1 + off);
        }
        const float (*Asb)[BM + PAD] = As[buf];
        const float (*Bsb)[BN + PAD] = Bs[buf];
#pragma unroll
        for (int kk = 0; kk < BK; ++kk) {
            float4 av0 = *(const float4*)(&Asb[kk][tx * 4]);
            float4 av1 = *(const float4*)(&Asb[kk][tx * 4 + 64]);
            float4 bv0 = *(const float4*)(&Bsb[kk][ty * 4]);
            float4 bv1 = *(const float4*)(&Bsb[kk][ty * 4 + 64]);
            ull ap[4];
            ap[0] = ((const ull*)&av0)[0];
            ap[1] = ((const ull*)&av0)[1];
            ap[2] = ((const ull*)&av1)[0];
            ap[3] = ((const ull*)&av1)[1];
            ull bb[8];
            bb[0] = dup2(bv0.x); bb[1] = dup2(bv0.y);
            bb[2] = dup2(bv0.z); bb[3] = dup2(bv0.w);
            bb[4] = dup2(bv1.x); bb[5] = dup2(bv1.y);
            bb[6] = dup2(bv1.z); bb[7] = dup2(bv1.w);
#pragma unroll
            for (int p = 0; p < 4; ++p)
#pragma unroll
                for (int j = 0; j < 8; ++j)
                    ffma2(acc2[p][j], ap[p], bb[j]);
        }
        if (it + 1 < nt) {
            const int nb = buf ^ 1;
            As[nb][acol + 0][arow] = a0.x; As[nb][acol + 1][arow] = a0.y;
            As[nb][acol + 2][arow] = a0.z; As[nb][acol + 3][arow] = a0.w;
            As[nb][acol + 0][arow + 64] = a1.x; As[nb][acol + 1][arow + 64] = a1.y;
            As[nb][acol + 2][arow + 64] = a1.z; As[nb][acol + 3][arow + 64] = a1.w;
            Bs[nb][acol + 0][arow] = b0.x; Bs[nb][acol + 1][arow] = b0.y;
            Bs[nb][acol + 2][arow] = b0.z; Bs[nb][acol + 3][arow] = b0.w;
            Bs[nb][acol + 0][arow + 64] = b1.x; Bs[nb][acol + 1][arow + 64] = b1.y;
            Bs[nb][acol + 2][arow + 64] = b1.z; Bs[nb][acol + 3][arow + 64] = b1.w;
            __syncthreads();
            buf = nb;
        }
    }

#pragma unroll
    for (int p = 0; p < 4; ++p) {
#pragma unroll
        for (int half = 0; half < 2; ++half) {
            const long long row = bm + (p >> 1) * 64 + tx * 4 + (p & 1) * 2 + half;
#pragma unroll
            for (int jm = 0; jm < 2; ++jm) {
                F2u v0, v1, v2, v3;
                v0.u = acc2[p][jm * 4 + 0];
                v1.u = acc2[p][jm * 4 + 1];
                v2.u = acc2[p][jm * 4 + 2];
                v3.u = acc2[p][jm * 4 + 3];
                float4 o = half ? make_float4(v0.f.y, v1.f.y, v2.f.y, v3.f.y)
                                : make_float4(v0.f.x, v1.f.x, v2.f.x, v3.f.x);
                *(float4*)(C + row * ldc + bn + jm * 64 + ty * 4) = o;
            }
        }
    }
}

// ============================================================
// TN body: C[m,n] = sum_k A[k,m]*B[k,n], double-buffered smem
// ============================================================
__device__ __forceinline__ void tn128_body(
    const float* __restrict__ A, const float* __restrict__ B, float* __restrict__ C,
    int K, int lda, int ldb, int ldc, int bm, int bn)
{
    __shared__ float As[2][BK][BM + PAD];
    __shared__ float Bs[2][BK][BN + PAD];
    const int tid = threadIdx.x;
    const int tx = tid & 15;
    const int ty = tid >> 4;
    const int krow = tid >> 5;          // 0..7
    const int ccol = (tid & 31) * 4;    // 0..124

    const float* Ap0 = A + (long long)(krow)     * lda + bm + ccol;
    const float* Ap1 = A + (long long)(krow + 8) * lda + bm + ccol;
    const float* Bp0 = B + (long long)(krow)     * ldb + bn + ccol;
    const float* Bp1 = B + (long long)(krow + 8) * ldb + bn + ccol;
    const long long stA = (long long)BK * lda;
    const long long stB = (long long)BK * ldb;

    float4 a0 = *(const float4*)Ap0;
    float4 a1 = *(const float4*)Ap1;
    float4 b0 = *(const float4*)Bp0;
    float4 b1 = *(const float4*)Bp1;

    ull acc2[4][8] = {};
    const int nt = K / BK;
    int buf = 0;

    *(float4*)(&As[0][krow][ccol])     = a0;
    *(float4*)(&As[0][krow + 8][ccol]) = a1;
    *(float4*)(&Bs[0][krow][ccol])     = b0;
    *(float4*)(&Bs[0][krow + 8][ccol]) = b1;
    __syncthreads();

    for (int it = 0; it < nt; ++it) {
        if (it + 1 < nt) {
            const long long offA = (long long)(it + 1) * stA;
            const long long offB = (long long)(it + 1) * stB;
            a0 = *(const float4*)(Ap0 + offA);
            a1 = *(const float4*)(Ap1 + offA);
            b0 = *(const float4*)(Bp0 + offB);
            b1 = *(const float4*)(Bp1 + offB);
        }
        const float (*Asb)[BM + PAD] = As[buf];
        const float (*Bsb)[BN + PAD] = Bs[buf];
#pragma unroll
        for (int kk = 0; kk < BK; ++kk) {
            float4 av0 = *(const float4*)(&Asb[kk][tx * 4]);
            float4 av1 = *(const float4*)(&Asb[kk][tx * 4 + 64]);
            float4 bv0 = *(const float4*)(&Bsb[kk][ty * 4]);
            float4 bv1 = *(const float4*)(&Bsb[kk][ty * 4 + 64]);
            ull ap[4];
            ap[0] = ((const ull*)&av0)[0];
            ap[1] = ((const ull*)&av0)[1];
            ap[2] = ((const ull*)&av1)[0];
            ap[3] = ((const ull*)&av1)[1];
            ull bb[8];
            bb[0] = dup2(bv0.x); bb[1] = dup2(bv0.y);
            bb[2] = dup2(bv0.z); bb[3] = dup2(bv0.w);
            bb[4] = dup2(bv1.x); bb[5] = dup2(bv1.y);
            bb[6] = dup2(bv1.z); bb[7] = dup2(bv1.w);
#pragma unroll
            for (int p = 0; p < 4; ++p)
#pragma unroll
                for (int j = 0; j < 8; ++j)
                    ffma2(acc2[p][j], ap[p], bb[j]);
        }
        if (it + 1 < nt) {
            const int nb = buf ^ 1;
            *(float4*)(&As[nb][krow][ccol])     = a0;
            *(float4*)(&As[nb][krow + 8][ccol]) = a1;
            *(float4*)(&Bs[nb][krow][ccol])     = b0;
            *(float4*)(&Bs[nb][krow + 8][ccol]) = b1;
            __syncthreads();
            buf = nb;
        }
    }

#pragma unroll
    for (int p = 0; p < 4; ++p) {
#pragma unroll
        for (int half = 0; half < 2; ++half) {
            const long long row = bm + (p >> 1) * 64 + tx * 4 + (p & 1) * 2 + half;
#pragma unroll
            for (int jm = 0; jm < 2; ++jm) {
                F2u v0, v1, v2, v3;
                v0.u = acc2[p][jm * 4 + 0];
                v1.u = acc2[p][jm * 4 + 1];
                v2.u = acc2[p][jm * 4 + 2];
                v3.u = acc2[p][jm * 4 + 3];
                float4 o = half ? make_float4(v0.f.y, v1.f.y, v2.f.y, v3.f.y)
                                : make_float4(v0.f.x, v1.f.x, v2.f.x, v3.f.x);
                *(float4*)(C + row * ldc + bn + jm * 64 + ty * 4) = o;
            }
        }
    }
}

// ============================================================
// 64x64 NT body, double-buffered
// ============================================================
#define SM_ 64
#define SK_ 16
__device__ __forceinline__ void nt64_body(
    const float* __restrict__ A, const float* __restrict__ B, float* __restrict__ C,
    int K, int lda, int ldb, int ldc, int bm, int bn)
{
    __shared__ float As[2][SK_][SM_];
    __shared__ float Bs[2][SK_][SM_];
    const int tid = threadIdx.x;
    const int tx = tid & 15;
    const int ty = tid >> 4;
    const int lrow = tid >> 2;
    const int lcol = (tid & 3) * 4;

    const float* Ap = A + (long long)(bm + lrow) * lda + lcol;
    const float* Bp = B + (long long)(bn + lrow) * ldb + lcol;

    float4 a = *(const float4*)Ap;
    float4 b = *(const float4*)Bp;

    ull acc2[2][4] = {};
    const int nt = K / SK_;
    int buf = 0;

    As[0][lcol + 0][lrow] = a.x; As[0][lcol + 1][lrow] = a.y;
    As[0][lcol + 2][lrow] = a.z; As[0][lcol + 3][lrow] = a.w;
    Bs[0][lcol + 0][lrow] = b.x; Bs[0][lcol + 1][lrow] = b.y;
    Bs[0][lcol + 2][lrow] = b.z; Bs[0][lcol + 3][lrow] = b.w;
    __syncthreads();

    for (int it = 0; it < nt; ++it) {
        if (it + 1 < nt) {
            const int off = (it + 1) * SK_;
            a = *(const float4*)(Ap + off);
            b = *(const float4*)(Bp + off);
        }
        const float (*Asb)[SM_] = As[buf];
        const float (*Bsb)[SM_] = Bs[buf];
#pragma unroll
        for (int kk = 0; kk < SK_; ++kk) {
            float4 av = *(const float4*)(&Asb[kk][ty * 4]);
            float4 bv = *(const float4*)(&Bsb[kk][tx * 4]);
            ull ap[2];
            ap[0] = ((const ull*)&av)[0];
            ap[1] = ((const ull*)&av)[1];
            ull bb[4];
            bb[0] = dup2(bv.x); bb[1] = dup2(bv.y);
            bb[2] = dup2(bv.z); bb[3] = dup2(bv.w);
#pragma unroll
            for (int p = 0; p < 2; ++p)
#pragma unroll
                for (int j = 0; j < 4; ++j)
                    ffma2(acc2[p][j], ap[p], bb[j]);
        }
        if (it + 1 < nt) {
            const int nb = buf ^ 1;
            As[nb][lcol + 0][lrow] = a.x; As[nb][lcol + 1][lrow] = a.y;
            As[nb][lcol + 2][lrow] = a.z; As[nb][lcol + 3][lrow] = a.w;
            Bs[nb][lcol + 0][lrow] = b.x; Bs[nb][lcol + 1][lrow] = b.y;
            Bs[nb][lcol + 2][lrow] = b.z; Bs[nb][lcol + 3][lrow] = b.w;
            __syncthreads();
            buf = nb;
        }
    }

#pragma unroll
    for (int p = 0; p < 2; ++p) {
#pragma unroll
        for (int half = 0; half < 2; ++half) {
            const int crow = bm + ty * 4 + p * 2 + half;
            F2u v0, v1, v2, v3;
            v0.u = acc2[p][0]; v1.u = acc2[p][1];
            v2.u = acc2[p][2]; v3.u = acc2[p][3];
            float4 o = half ? make_float4(v0.f.y, v1.f.y, v2.f.y, v3.f.y)
                            : make_float4(v0.f.x, v1.f.x, v2.f.x, v3.f.x);
            *(float4*)(C + (long long)crow * ldc + bn + tx * 4) = o;
        }
    }
}

// ============================================================
// GEMM kernels (wrappers)
// ============================================================

// Generic strided-batch NT (logits, final w_o projection)
__global__ __launch_bounds__(256) void gemm_nt128(
    const float* __restrict__ A, const float* __restrict__ B, float* __restrict__ C,
    int K, int lda, int ldb, int ldc,
    long long sA, long long sB, long long sC)
{
    nt128_body(A + (long long)blockIdx.z * sA, B + (long long)blockIdx.z * sB,
               C + (long long)blockIdx.z * sC,
               K, lda, ldb, ldc, blockIdx.y * BM, blockIdx.x * BN);
}

// Down-projections: z=0 -> ckv, z=1 -> cq
__global__ __launch_bounds__(256) void gemm_down(
    const float* __restrict__ h, const float* __restrict__ w_dkv,
    const float* __restrict__ w_dq, float* __restrict__ ckv, float* __restrict__ cq)
{
    const float* B = blockIdx.z ? w_dq : w_dkv;
    float* C = blockIdx.z ? cq : ckv;
    nt128_body(h, B, C, D, D, D, DC, blockIdx.y * BM, blockIdx.x * BN);
}

// Up-projections: z/16 selects {k, v, q}, z%16 = head
__global__ __launch_bounds__(256) void gemm_up(
    const float* __restrict__ ckv, const float* __restrict__ cq,
    const float* __restrict__ w_uk, const float* __restrict__ w_uv,
    const float* __restrict__ w_uq,
    float* __restrict__ k, float* __restrict__ v, float* __restrict__ q)
{
    const int sel = blockIdx.z >> 4;
    const int head = blockIdx.z & 15;
    const float* A = (sel == 2) ? cq : ckv;
    const float* B = (sel == 0 ? w_uk : (sel == 1 ? w_uv : w_uq)) + head * DC;
    float* C;
    int ldc;
    if (sel == 0)      { C = k + (long long)head * T * QKD; ldc = QKD; }
    else if (sel == 1) { C = v + (long long)head * T * DH;  ldc = DH;  }
    else               { C = q + (long long)head * T * QKD; ldc = QKD; }
    nt128_body(A, B, C, DC, DC, NH * DC, ldc, blockIdx.y * BM, 0);
}

// Attention output: out[n,l,e] = sum_t S[n,t,l] v[n,t,e]
__global__ __launch_bounds__(256) void gemm_attn(
    const float* __restrict__ logits, const float* __restrict__ v, float* __restrict__ attn)
{
    const long long z = blockIdx.z;
    tn128_body(logits + z * T * T, v + z * T * DH, attn + z * DH,
               T, T, DH, NH * DH, blockIdx.y * BM, 0);
}

// Small-N GEMMs: z<16 -> q_r per head; z==16 -> k_r
__global__ __launch_bounds__(256) void gemm_small(
    const float* __restrict__ h, const float* __restrict__ cq,
    const float* __restrict__ w_qr, const float* __restrict__ w_kr,
    float* __restrict__ q, float* __restrict__ kr)
{
    const float *A, *B;
    float* C;
    int K, lda, ldb, ldc;
    if (blockIdx.z == 16) {
        A = h; B = w_kr; C = kr; K = D; lda = D; ldb = D; ldc = DRH;
    } else {
        A = cq;
        B = w_qr + blockIdx.z * DC;
        C = q + DH + (long long)blockIdx.z * T * QKD;
        K = DC; lda = DC; ldb = NH * DC; ldc = QKD;
    }
    nt64_body(A, B, C, K, lda, ldb, ldc, blockIdx.y * SM_, 0);
}

// ============================================================
// Elementwise kernels
// ============================================================
__global__ void rope_q_kernel(float* __restrict__ q, const float* __restrict__ freqs)
{
    int idx = blockIdx.x * blockDim.x + threadIdx.x;   // NH*T*32
    int i = idx & 31;
    int t = (idx >> 5) & (T - 1);
    int n = idx >> 16;
    float ang = freqs[t * (DRH / 2) + i];
    float c, s;
    __sincosf(ang, &s, &c);
    float* base = q + ((size_t)(n * T + t)) * QKD + DH;
    float re = base[i], im = base[i + 32];
    base[i]      = re * c - im * s;
    base[i + 32] = re * s + im * c;
}

__global__ void rope_k_bcast_kernel(const float* __restrict__ kr, float* __restrict__ kbuf,
                                    const float* __restrict__ freqs)
{
    int idx = blockIdx.x * blockDim.x + threadIdx.x;   // T*32
    int i = idx & 31;
    int t = idx >> 5;
    float ang = freqs[t * (DRH / 2) + i];
    float c, s;
    __sincosf(ang, &s, &c);
    float re = kr[t * DRH + i], im = kr[t * DRH + 32 + i];
    const float inv_nh = 1.0f / (float)NH;
    float rr = (re * c - im * s) * inv_nh;
    float ri = (re * s + im * c) * inv_nh;
#pragma unroll
    for (int n = 0; n < NH; ++n) {
        float* b = kbuf + ((size_t)(n * T + t)) * QKD + DH;
        b[i]      = rr;
        b[i + 32] = ri;
    }
}

__global__ void wo_transpose_kernel(const float* __restrict__ wo, float* __restrict__ wt)
{
    int idx = blockIdx.x * blockDim.x + threadIdx.x;   // D * NH * DH
    int j = idx & (NH * DH - 1);
    int d = idx >> 11;
    int n = j >> 7;
    int e = j & (DH - 1);
    wt[idx] = wo[(size_t)d * (DH * NH) + e * NH + n];
}

__global__ __launch_bounds__(256) void softmax_kernel(
    float* __restrict__ logits, const float* __restrict__ mask, float scale)
{
    const int t = blockIdx.x;
    const int n = blockIdx.y;
    float* __restrict__ row = logits + ((size_t)n * T + t) * T;
    const float* __restrict__ mrow = mask + (size_t)t * T;
    const int tid = threadIdx.x;

    float v[8];
    float mx = -1e30f;
#pragma unroll
    for (int j = 0; j < 8; ++j) {
        int l = tid + j * 256;
        v[j] = fmaf(row[l], scale, mrow[l]);
        mx = fmaxf(mx, v[j]);
    }
    __shared__ float redm[8], reds[8];
#pragma unroll
    for (int o = 16; o; o >>= 1) mx = fmaxf(mx, __shfl_xor_sync(0xffffffffu, mx, o));
    if ((tid & 31) == 0) redm[tid >> 5] = mx;
    __syncthreads();
    mx = redm[0];
#pragma unroll
    for (int w = 1; w < 8; ++w) mx = fmaxf(mx, redm[w]);

    float sum = 0.0f;
#pragma unroll
    for (int j = 0; j < 8; ++j) {
        v[j] = __expf(v[j] - mx);
        sum += v[j];
    }
#pragma unroll
    for (int o = 16; o; o >>= 1) sum += __shfl_xor_sync(0xffffffffu, sum, o);
    if ((tid & 31) == 0) reds[tid >> 5] = sum;
    __syncthreads();
    sum = reds[0];
#pragma unroll
    for (int w = 1; w < 8; ++w) sum += reds[w];

    float inv = 1.0f / sum;
#pragma unroll
    for (int j = 0; j < 8; ++j)
        row[tid + j * 256] = v[j] * inv;
}

// ============================================================
// Launch
// ============================================================
extern "C" void kernel_launch(void* const* d_in, const int* in_sizes, int n_in,
                              void* d_out, int out_size)
{
    const float* h     = (const float*)d_in[0];
    const float* freqs = (const float*)d_in[1];
    const float* mask  = (const float*)d_in[2];
    const float* w_dkv = (const float*)d_in[3];
    const float* w_uk  = (const float*)d_in[4];
    const float* w_uv  = (const float*)d_in[5];
    const float* w_dq  = (const float*)d_in[6];
    const float* w_uq  = (const float*)d_in[7];
    const float* w_qr  = (const float*)d_in[8];
    const float* w_kr  = (const float*)d_in[9];
    const float* w_o   = (const float*)d_in[10];
    float* out = (float*)d_out;
    (void)in_sizes; (void)n_in; (void)out_size;

    float *ckv, *cq, *q, *k, *v, *kr, *logits, *attn, *wot;
    cudaGetSymbolAddress((void**)&ckv,    g_ckv);
    cudaGetSymbolAddress((void**)&cq,     g_cq);
    cudaGetSymbolAddress((void**)&q,      g_q);
    cudaGetSymbolAddress((void**)&k,      g_k);
    cudaGetSymbolAddress((void**)&v,      g_v);
    cudaGetSymbolAddress((void**)&kr,     g_kr);
    cudaGetSymbolAddress((void**)&logits, g_logits);
    cudaGetSymbolAddress((void**)&attn,   g_attn);
    cudaGetSymbolAddress((void**)&wot,    g_wot);

    const dim3 blk(256);
    const long long sQ = (long long)T * QKD;

    // w_o permute (independent; do it first)
    wo_transpose_kernel<<<(D * NH * DH) / 256, 256>>>(w_o, wot);

    // Down-projections: ckv + cq in one launch
    gemm_down<<<dim3(DC / BN, T / BM, 2), blk>>>(h, w_dkv, w_dq, ckv, cq);

    // Up-projections: k, v, q in one launch (z = 48)
    gemm_up<<<dim3(1, T / BM, 3 * NH), blk>>>(ckv, cq, w_uk, w_uv, w_uq, k, v, q);

    // q_r (16 heads) + k_r in one launch (z = 17)
    gemm_small<<<dim3(1, T / SM_, NH + 1), blk>>>(h, cq, w_qr, w_kr, q, kr);

    // Rope
    rope_q_kernel<<<(NH * T * 32) / 256, 256>>>(q, freqs);
    rope_k_bcast_kernel<<<(T * 32) / 256, 256>>>(kr, k, freqs);

    // logits[n,t,l] = q . k   (M=N=2048, K=192)
    gemm_nt128<<<dim3(T / BN, T / BM, NH), blk>>>(q, k, logits, QKD, QKD, QKD, T, sQ, sQ, (long long)T * T);

    // softmax over l with mask, scale = 1/sqrt(192)
    softmax_kernel<<<dim3(T, NH), 256>>>(logits, mask, 0.07216878364870323f);

    // out[n,l,e] = sum_t S[n,t,l] v[n,t,e]
    gemm_attn<<<dim3(1, T / BM, NH), blk>>>(logits, v, attn);

    // Final projection (M=2048, N=2048, K=2048)
    gemm_nt128<<<dim3(D / BN, T / BM, 1), blk>>>(attn, wot, out, NH * DH, NH * DH, NH * DH, D, 0, 0, 0);
}

// round 7
// speedup vs baseline: 1.2824x; 1.2824x over previous
#include <cuda_runtime.h>
#include <cuda_bf16.h>

// Problem constants
#define T   2048
#define D   2048
#define NH  16
#define DH  128
#define DRH 64
#define DC  512
#define QKD 192   // DH + DRH

// -------- scratch (device globals; no allocation allowed) --------
__device__ float g_ckv[(size_t)T * DC];
__device__ float g_cq [(size_t)T * DC];
__device__ float g_q  [(size_t)NH * T * QKD];
__device__ float g_k  [(size_t)NH * T * QKD];
__device__ float g_v  [(size_t)NH * T * DH];
__device__ float g_kr [(size_t)T * DRH];
__device__ float g_logits[(size_t)NH * T * T];
__device__ float g_attn[(size_t)T * NH * DH];
__device__ float g_wot [(size_t)D * NH * DH];

typedef unsigned long long ull;

__device__ __forceinline__ void ffma2(ull& d, ull a, ull b) {
    asm("fma.rn.f32x2 %0, %1, %2, %0;" : "+l"(d) : "l"(a), "l"(b));
}
__device__ __forceinline__ ull dup2(float x) {
    ull r;
    asm("mov.b64 %0, {%1, %1};" : "=l"(r) : "f"(x));
    return r;
}
union F2u { ull u; float2 f; };

#define BM 128
#define BN 128
#define BK 16
#define PAD 4

// ============================================================
// NT: C[m,n] = sum_k A[m,k]*B[n,k], double-buffered smem
// ============================================================
__global__ __launch_bounds__(256) void gemm_nt128(
    const float* __restrict__ A, const float* __restrict__ B, float* __restrict__ C,
    int K, int lda, int ldb, int ldc,
    long long sA, long long sB, long long sC)
{
    __shared__ float As[2][BK][BM + PAD];
    __shared__ float Bs[2][BK][BN + PAD];
    A += (long long)blockIdx.z * sA;
    B += (long long)blockIdx.z * sB;
    C += (long long)blockIdx.z * sC;
    const int bm = blockIdx.y * BM;
    const int bn = blockIdx.x * BN;
    const int tid = threadIdx.x;
    const int tx = tid & 15;
    const int ty = tid >> 4;
    const int arow = tid >> 2;
    const int acol = (tid & 3) * 4;

    const float* Ap0 = A + (long long)(bm + arow)      * lda + acol;
    const float* Ap1 = A + (long long)(bm + arow + 64) * lda + acol;
    const float* Bp0 = B + (long long)(bn + arow)      * ldb + acol;
    const float* Bp1 = B + (long long)(bn + arow + 64) * ldb + acol;

    float4 a0 = *(const float4*)Ap0;
    float4 a1 = *(const float4*)Ap1;
    float4 b0 = *(const float4*)Bp0;
    float4 b1 = *(const float4*)Bp1;

    ull acc2[4][8] = {};
    const int nt = K / BK;
    int buf = 0;

    As[0][acol + 0][arow] = a0.x; As[0][acol + 1][arow] = a0.y;
    As[0][acol + 2][arow] = a0.z; As[0][acol + 3][arow] = a0.w;
    As[0][acol + 0][arow + 64] = a1.x; As[0][acol + 1][arow + 64] = a1.y;
    As[0][acol + 2][arow + 64] = a1.z; As[0][acol + 3][arow + 64] = a1.w;
    Bs[0][acol + 0][arow] = b0.x; Bs[0][acol + 1][arow] = b0.y;
    Bs[0][acol + 2][arow] = b0.z; Bs[0][acol + 3][arow] = b0.w;
    Bs[0][acol + 0][arow + 64] = b1.x; Bs[0][acol + 1][arow + 64] = b1.y;
    Bs[0][acol + 2][arow + 64] = b1.z; Bs[0][acol + 3][arow + 64] = b1.w;
    __syncthreads();

    for (int it = 0; it < nt; ++it) {
        if (it + 1 < nt) {
            const int off = (it + 1) * BK;
            a0 = *(const float4*)(Ap0 + off);
            a1 = *(const float4*)(Ap1 + off);
            b0 = *(const float4*)(Bp0 + off);
            b1 = *(const float4*)(Bp1 + off);
        }
        const float (*Asb)[BM + PAD] = As[buf];
        const float (*Bsb)[BN + PAD] = Bs[buf];
#pragma unroll
        for (int kk = 0; kk < BK; ++kk) {
            float4 av0 = *(const float4*)(&Asb[kk][tx * 4]);
            float4 av1 = *(const float4*)(&Asb[kk][tx * 4 + 64]);
            float4 bv0 = *(const float4*)(&Bsb[kk][ty * 4]);
            float4 bv1 = *(const float4*)(&Bsb[kk][ty * 4 + 64]);
            ull ap[4];
            ap[0] = ((const ull*)&av0)[0];
            ap[1] = ((const ull*)&av0)[1];
            ap[2] = ((const ull*)&av1)[0];
            ap[3] = ((const ull*)&av1)[1];
            ull bb[8];
            bb[0] = dup2(bv0.x); bb[1] = dup2(bv0.y);
            bb[2] = dup2(bv0.z); bb[3] = dup2(bv0.w);
            bb[4] = dup2(bv1.x); bb[5] = dup2(bv1.y);
            bb[6] = dup2(bv1.z); bb[7] = dup2(bv1.w);
#pragma unroll
            for (int p = 0; p < 4; ++p)
#pragma unroll
                for (int j = 0; j < 8; ++j)
                    ffma2(acc2[p][j], ap[p], bb[j]);
        }
        if (it + 1 < nt) {
            const int nb = buf ^ 1;
            As[nb][acol + 0][arow] = a0.x; As[nb][acol + 1][arow] = a0.y;
            As[nb][acol + 2][arow] = a0.z; As[nb][acol + 3][arow] = a0.w;
            As[nb][acol + 0][arow + 64] = a1.x; As[nb][acol + 1][arow + 64] = a1.y;
            As[nb][acol + 2][arow + 64] = a1.z; As[nb][acol + 3][arow + 64] = a1.w;
            Bs[nb][acol + 0][arow] = b0.x; Bs[nb][acol + 1][arow] = b0.y;
            Bs[nb][acol + 2][arow] = b0.z; Bs[nb][acol + 3][arow] = b0.w;
            Bs[nb][acol + 0][arow + 64] = b1.x; Bs[nb][acol + 1][arow + 64] = b1.y;
            Bs[nb][acol + 2][arow + 64] = b1.z; Bs[nb][acol + 3][arow + 64] = b1.w;
            __syncthreads();
            buf = nb;
        }
    }

#pragma unroll
    for (int p = 0; p < 4; ++p) {
#pragma unroll
        for (int half = 0; half < 2; ++half) {
            const long long row = bm + (p >> 1) * 64 + tx * 4 + (p & 1) * 2 + half;
#pragma unroll
            for (int jm = 0; jm < 2; ++jm) {
                F2u v0, v1, v2, v3;
                v0.u = acc2[p][jm * 4 + 0];
                v1.u = acc2[p][jm * 4 + 1];
                v2.u = acc2[p][jm * 4 + 2];
                v3.u = acc2[p][jm * 4 + 3];
                float4 o = half ? make_float4(v0.f.y, v1.f.y, v2.f.y, v3.f.y)
                                : make_float4(v0.f.x, v1.f.x, v2.f.x, v3.f.x);
                *(float4*)(C + row * ldc + bn + jm * 64 + ty * 4) = o;
            }
        }
    }
}

// ============================================================
// TN: C[m,n] = sum_k A[k,m]*B[k,n], double-buffered smem
// ============================================================
__global__ __launch_bounds__(256) void gemm_tn128(
    const float* __restrict__ A, const float* __restrict__ B, float* __restrict__ C,
    int K, int lda, int ldb, int ldc,
    long long sA, long long sB, long long sC)
{
    __shared__ float As[2][BK][BM + PAD];
    __shared__ float Bs[2][BK][BN + PAD];
    A += (long long)blockIdx.z * sA;
    B += (long long)blockIdx.z * sB;
    C += (long long)blockIdx.z * sC;
    const int bm = blockIdx.y * BM;
    const int bn = blockIdx.x * BN;
    const int tid = threadIdx.x;
    const int tx = tid & 15;
    const int ty = tid >> 4;
    const int krow = tid >> 5;          // 0..7
    const int ccol = (tid & 31) * 4;    // 0..124

    const float* Ap0 = A + (long long)(krow)     * lda + bm + ccol;
    const float* Ap1 = A + (long long)(krow + 8) * lda + bm + ccol;
    const float* Bp0 = B + (long long)(krow)     * ldb + bn + ccol;
    const float* Bp1 = B + (long long)(krow + 8) * ldb + bn + ccol;
    const long long stA = (long long)BK * lda;
    const long long stB = (long long)BK * ldb;

    float4 a0 = *(const float4*)Ap0;
    float4 a1 = *(const float4*)Ap1;
    float4 b0 = *(const float4*)Bp0;
    float4 b1 = *(const float4*)Bp1;

    ull acc2[4][8] = {};
    const int nt = K / BK;
    int buf = 0;

    *(float4*)(&As[0][krow][ccol])     = a0;
    *(float4*)(&As[0][krow + 8][ccol]) = a1;
    *(float4*)(&Bs[0][krow][ccol])     = b0;
    *(float4*)(&Bs[0][krow + 8][ccol]) = b1;
    __syncthreads();

    for (int it = 0; it < nt; ++it) {
        if (it + 1 < nt) {
            const long long offA = (long long)(it + 1) * stA;
            const long long offB = (long long)(it + 1) * stB;
            a0 = *(const float4*)(Ap0 + offA);
            a1 = *(const float4*)(Ap1 + offA);
            b0 = *(const float4*)(Bp0 + offB);
            b1 = *(const float4*)(Bp1 + offB);
        }
        const float (*Asb)[BM + PAD] = As[buf];
        const float (*Bsb)[BN + PAD] = Bs[buf];
#pragma unroll
        for (int kk = 0; kk < BK; ++kk) {
            float4 av0 = *(const float4*)(&Asb[kk][tx * 4]);
            float4 av1 = *(const float4*)(&Asb[kk][tx * 4 + 64]);
            float4 bv0 = *(const float4*)(&Bsb[kk][ty * 4]);
            float4 bv1 = *(const float4*)(&Bsb[kk][ty * 4 + 64]);
            ull ap[4];
            ap[0] = ((const ull*)&av0)[0];
            ap[1] = ((const ull*)&av0)[1];
            ap[2] = ((const ull*)&av1)[0];
            ap[3] = ((const ull*)&av1)[1];
            ull bb[8];
            bb[0] = dup2(bv0.x); bb[1] = dup2(bv0.y);
            bb[2] = dup2(bv0.z); bb[3] = dup2(bv0.w);
            bb[4] = dup2(bv1.x); bb[5] = dup2(bv1.y);
            bb[6] = dup2(bv1.z); bb[7] = dup2(bv1.w);
#pragma unroll
            for (int p = 0; p < 4; ++p)
#pragma unroll
                for (int j = 0; j < 8; ++j)
                    ffma2(acc2[p][j], ap[p], bb[j]);
        }
        if (it + 1 < nt) {
            const int nb = buf ^ 1;
            *(float4*)(&As[nb][krow][ccol])     = a0;
            *(float4*)(&As[nb][krow + 8][ccol]) = a1;
            *(float4*)(&Bs[nb][krow][ccol])     = b0;
            *(float4*)(&Bs[nb][krow + 8][ccol]) = b1;
            __syncthreads();
            buf = nb;
        }
    }

#pragma unroll
    for (int p = 0; p < 4; ++p) {
#pragma unroll
        for (int half = 0; half < 2; ++half) {
            const long long row = bm + (p >> 1) * 64 + tx * 4 + (p & 1) * 2 + half;
#pragma unroll
            for (int jm = 0; jm < 2; ++jm) {
                F2u v0, v1, v2, v3;
                v0.u = acc2[p][jm * 4 + 0];
                v1.u = acc2[p][jm * 4 + 1];
                v2.u = acc2[p][jm * 4 + 2];
                v3.u = acc2[p][jm * 4 + 3];
                float4 o = half ? make_float4(v0.f.y, v1.f.y, v2.f.y, v3.f.y)
                                : make_float4(v0.f.x, v1.f.x, v2.f.x, v3.f.x);
                *(float4*)(C + row * ldc + bn + jm * 64 + ty * 4) = o;
            }
        }
    }
}

// ============================================================
// 64x64 GEMM (for N=64 cases: k_r, q_r), single-buffer (as in R3)
// ============================================================
#define SM_ 64
#define SK_ 16
__global__ __launch_bounds__(256) void gemm_nt64(
    const float* __restrict__ A, const float* __restrict__ B, float* __restrict__ C,
    int K, int lda, int ldb, int ldc,
    long long sA, long long sB, long long sC)
{
    __shared__ float As[SK_][SM_];
    __shared__ float Bs[SK_][SM_];
    A += (long long)blockIdx.z * sA;
    B += (long long)blockIdx.z * sB;
    C += (long long)blockIdx.z * sC;
    const int bm = blockIdx.y * SM_;
    const int bn = blockIdx.x * SM_;
    const int tid = threadIdx.x;
    const int tx = tid & 15;
    const int ty = tid >> 4;
    const int lrow = tid >> 2;
    const int lcol = (tid & 3) * 4;

    ull acc2[2][4] = {};

    for (int k0 = 0; k0 < K; k0 += SK_) {
        float4 a = *(const float4*)(A + (long long)(bm + lrow) * lda + k0 + lcol);
        float4 b = *(const float4*)(B + (long long)(bn + lrow) * ldb + k0 + lcol);
        __syncthreads();
        As[lcol + 0][lrow] = a.x; As[lcol + 1][lrow] = a.y;
        As[lcol + 2][lrow] = a.z; As[lcol + 3][lrow] = a.w;
        Bs[lcol + 0][lrow] = b.x; Bs[lcol + 1][lrow] = b.y;
        Bs[lcol + 2][lrow] = b.z; Bs[lcol + 3][lrow] = b.w;
        __syncthreads();
#pragma unroll
        for (int kk = 0; kk < SK_; ++kk) {
            float4 av = *(const float4*)(&As[kk][ty * 4]);
            float4 bv = *(const float4*)(&Bs[kk][tx * 4]);
            ull ap[2];
            ap[0] = ((const ull*)&av)[0];
            ap[1] = ((const ull*)&av)[1];
            ull bb[4];
            bb[0] = dup2(bv.x); bb[1] = dup2(bv.y);
            bb[2] = dup2(bv.z); bb[3] = dup2(bv.w);
#pragma unroll
            for (int p = 0; p < 2; ++p)
#pragma unroll
                for (int j = 0; j < 4; ++j)
                    ffma2(acc2[p][j], ap[p], bb[j]);
        }
    }

#pragma unroll
    for (int p = 0; p < 2; ++p) {
#pragma unroll
        for (int half = 0; half < 2; ++half) {
            const int crow = bm + ty * 4 + p * 2 + half;
            F2u v0, v1, v2, v3;
            v0.u = acc2[p][0]; v1.u = acc2[p][1];
            v2.u = acc2[p][2]; v3.u = acc2[p][3];
            float4 o = half ? make_float4(v0.f.y, v1.f.y, v2.f.y, v3.f.y)
                            : make_float4(v0.f.x, v1.f.x, v2.f.x, v3.f.x);
            *(float4*)(C + (long long)crow * ldc + bn + tx * 4) = o;
        }
    }
}

// ============================================================
// Elementwise kernels
// ============================================================
__global__ void rope_q_kernel(float* __restrict__ q, const float* __restrict__ freqs)
{
    int idx = blockIdx.x * blockDim.x + threadIdx.x;   // NH*T*32
    int i = idx & 31;
    int t = (idx >> 5) & (T - 1);
    int n = idx >> 16;
    float ang = freqs[t * (DRH / 2) + i];
    float c, s;
    __sincosf(ang, &s, &c);
    float* base = q + ((size_t)(n * T + t)) * QKD + DH;
    float re = base[i], im = base[i + 32];
    base[i]      = re * c - im * s;
    base[i + 32] = re * s + im * c;
}

__global__ void rope_k_bcast_kernel(const float* __restrict__ kr, float* __restrict__ kbuf,
                                    const float* __restrict__ freqs)
{
    int idx = blockIdx.x * blockDim.x + threadIdx.x;   // T*32
    int i = idx & 31;
    int t = idx >> 5;
    float ang = freqs[t * (DRH / 2) + i];
    float c, s;
    __sincosf(ang, &s, &c);
    float re = kr[t * DRH + i], im = kr[t * DRH + 32 + i];
    const float inv_nh = 1.0f / (float)NH;
    float rr = (re * c - im * s) * inv_nh;
    float ri = (re * s + im * c) * inv_nh;
#pragma unroll
    for (int n = 0; n < NH; ++n) {
        float* b = kbuf + ((size_t)(n * T + t)) * QKD + DH;
        b[i]      = rr;
        b[i + 32] = ri;
    }
}

__global__ void wo_transpose_kernel(const float* __restrict__ wo, float* __restrict__ wt)
{
    int idx = blockIdx.x * blockDim.x + threadIdx.x;   // D * NH * DH
    int j = idx & (NH * DH - 1);
    int d = idx >> 11;
    int n = j >> 7;
    int e = j & (DH - 1);
    wt[idx] = wo[(size_t)d * (DH * NH) + e * NH + n];
}

__global__ __launch_bounds__(256) void softmax_kernel(
    float* __restrict__ logits, const float* __restrict__ mask, float scale)
{
    const int t = blockIdx.x;
    const int n = blockIdx.y;
    float* __restrict__ row = logits + ((size_t)n * T + t) * T;
    const float* __restrict__ mrow = mask + (size_t)t * T;
    const int tid = threadIdx.x;

    float v[8];
    float mx = -1e30f;
#pragma unroll
    for (int j = 0; j < 8; ++j) {
        int l = tid + j * 256;
        v[j] = fmaf(row[l], scale, mrow[l]);
        mx = fmaxf(mx, v[j]);
    }
    __shared__ float redm[8], reds[8];
#pragma unroll
    for (int o = 16; o; o >>= 1) mx = fmaxf(mx, __shfl_xor_sync(0xffffffffu, mx, o));
    if ((tid & 31) == 0) redm[tid >> 5] = mx;
    __syncthreads();
    mx = redm[0];
#pragma unroll
    for (int w = 1; w < 8; ++w) mx = fmaxf(mx, redm[w]);

    float sum = 0.0f;
#pragma unroll
    for (int j = 0; j < 8; ++j) {
        v[j] = __expf(v[j] - mx);
        sum += v[j];
    }
#pragma unroll
    for (int o = 16; o; o >>= 1) sum += __shfl_xor_sync(0xffffffffu, sum, o);
    if ((tid & 31) == 0) reds[tid >> 5] = sum;
    __syncthreads();
    sum = reds[0];
#pragma unroll
    for (int w = 1; w < 8; ++w) sum += reds[w];

    float inv = 1.0f / sum;
#pragma unroll
    for (int j = 0; j < 8; ++j)
        row[tid + j * 256] = v[j] * inv;
}

// ============================================================
// Launch (same structure as R3)
// ============================================================
extern "C" void kernel_launch(void* const* d_in, const int* in_sizes, int n_in,
                              void* d_out, int out_size)
{
    const float* h     = (const float*)d_in[0];
    const float* freqs = (const float*)d_in[1];
    const float* mask  = (const float*)d_in[2];
    const float* w_dkv = (const float*)d_in[3];
    const float* w_uk  = (const float*)d_in[4];
    const float* w_uv  = (const float*)d_in[5];
    const float* w_dq  = (const float*)d_in[6];
    const float* w_uq  = (const float*)d_in[7];
    const float* w_qr  = (const float*)d_in[8];
    const float* w_kr  = (const float*)d_in[9];
    const float* w_o   = (const float*)d_in[10];
    float* out = (float*)d_out;
    (void)in_sizes; (void)n_in; (void)out_size;

    float *ckv, *cq, *q, *k, *v, *kr, *logits, *attn, *wot;
    cudaGetSymbolAddress((void**)&ckv,    g_ckv);
    cudaGetSymbolAddress((void**)&cq,     g_cq);
    cudaGetSymbolAddress((void**)&q,      g_q);
    cudaGetSymbolAddress((void**)&k,      g_k);
    cudaGetSymbolAddress((void**)&v,      g_v);
    cudaGetSymbolAddress((void**)&kr,     g_kr);
    cudaGetSymbolAddress((void**)&logits, g_logits);
    cudaGetSymbolAddress((void**)&attn,   g_attn);
    cudaGetSymbolAddress((void**)&wot,    g_wot);

    const dim3 blk(256);
    const long long sQ = (long long)T * QKD;

    // Latents: c_kv, c_q = h @ W^T   (M=2048, N=512, K=2048)
    gemm_nt128<<<dim3(DC / BN, T / BM, 1), blk>>>(h, w_dkv, ckv, D, D, D, DC, 0, 0, 0);
    gemm_nt128<<<dim3(DC / BN, T / BM, 1), blk>>>(h, w_dq,  cq,  D, D, D, DC, 0, 0, 0);
    // k_r (pre-rope): N=64
    gemm_nt64<<<dim3(1, T / SM_, 1), blk>>>(h, w_kr, kr, D, D, D, DRH, 0, 0, 0);

    // Per-head up-projections (N=128, K=512, batched over heads)
    gemm_nt128<<<dim3(1, T / BM, NH), blk>>>(ckv, w_uk, k, DC, DC, NH * DC, QKD, 0, DC, sQ);
    gemm_nt128<<<dim3(1, T / BM, NH), blk>>>(ckv, w_uv, v, DC, DC, NH * DC, DH,  0, DC, (long long)T * DH);
    gemm_nt128<<<dim3(1, T / BM, NH), blk>>>(cq,  w_uq, q, DC, DC, NH * DC, QKD, 0, DC, sQ);
    // q_r: N=64
    gemm_nt64<<<dim3(1, T / SM_, NH), blk>>>(cq, w_qr, q + DH, DC, DC, NH * DC, QKD, 0, DC, sQ);

    // Rope
    rope_q_kernel<<<(NH * T * 32) / 256, 256>>>(q, freqs);
    rope_k_bcast_kernel<<<(T * 32) / 256, 256>>>(kr, k, freqs);

    // logits[n,t,l] = q . k   (M=N=2048, K=192)
    gemm_nt128<<<dim3(T / BN, T / BM, NH), blk>>>(q, k, logits, QKD, QKD, QKD, T, sQ, sQ, (long long)T * T);

    // softmax over l with mask, scale = 1/sqrt(192)
    softmax_kernel<<<dim3(T, NH), 256>>>(logits, mask, 0.07216878364870323f);

    // out[n,l,e] = sum_t S[n,t,l] v[n,t,e]
    gemm_tn128<<<dim3(1, T / BM, NH), blk>>>(logits, v, attn, T, T, DH, NH * DH,
                                             (long long)T * T, (long long)T * DH, DH);

    // w_o permute then final projection (M=2048, N=2048, K=2048)
    wo_transpose_kernel<<<(D * NH * DH) / 256, 256>>>(w_o, wot);
    gemm_nt128<<<dim3(D / BN, T / BM, 1), blk>>>(attn, wot, out, NH * DH, NH * DH, NH * DH, D, 0, 0, 0);
}

// round 8
// speedup vs baseline: 1.8361x; 1.4318x over previous
#include <cuda_runtime.h>
#include <cuda_bf16.h>

// Problem constants
#define T   2048
#define D   2048
#define NH  16
#define DH  128
#define DRH 64
#define DC  512
#define QKD 192   // DH + DRH

// -------- scratch (device globals; no allocation allowed) --------
__device__ float g_ckv[(size_t)T * DC];
__device__ float g_cq [(size_t)T * DC];
__device__ float g_q  [(size_t)NH * T * QKD];
__device__ float g_k  [(size_t)NH * T * QKD];
__device__ float g_v  [(size_t)NH * T * DH];
__device__ float g_kr [(size_t)T * DRH];
__device__ float g_logits[(size_t)NH * T * T];
__device__ float g_attn[(size_t)T * NH * DH];
__device__ float g_wot [(size_t)D * NH * DH];

typedef unsigned long long ull;

__device__ __forceinline__ void ffma2(ull& d, ull a, ull b) {
    asm("fma.rn.f32x2 %0, %1, %2, %0;" : "+l"(d) : "l"(a), "l"(b));
}
__device__ __forceinline__ ull dup2(float x) {
    ull r;
    asm("mov.b64 %0, {%1, %1};" : "=l"(r) : "f"(x));
    return r;
}
union F2u { ull u; float2 f; };

// ============================================================
// TF32 tensor-core GEMM: 128x128x16 tile, 8 warps, warp = 64x32
// mma.sync.aligned.m16n8k8 tf32, fp32 accumulate.
// Fragment-major swizzled smem: 1 LDS.128 per A-frag, 1 LDS.64 per B-frag.
// ============================================================

__device__ __forceinline__ unsigned f2tf(float x) {
    unsigned r;
    asm("cvt.rna.tf32.f32 %0, %1;" : "=r"(r) : "f"(x));
    return r;
}

__device__ __forceinline__ void mma8(float* c, const unsigned* a, const unsigned* b) {
    asm("mma.sync.aligned.m16n8k8.row.col.f32.tf32.tf32.f32 "
        "{%0,%1,%2,%3}, {%4,%5,%6,%7}, {%8,%9}, {%0,%1,%2,%3};"
        : "+f"(c[0]), "+f"(c[1]), "+f"(c[2]), "+f"(c[3])
        : "r"(a[0]), "r"(a[1]), "r"(a[2]), "r"(a[3]), "r"(b[0]), "r"(b[1]));
}

// smem word index for A value (m in [0,128), k in [0,16)).
// Frag layout per (k8, mtile): 128 words = lane*4 + reg, swizzled.
__device__ __forceinline__ int a_word(int m, int k) {
    int t = (m & 7) * 4 + (k & 3);
    int r = (((k & 7) >> 2) << 1) | ((m >> 3) & 1);
    int k8 = k >> 3;
    int w = (t * 4) ^ (((t >> 2) & 7) << 2);
    return (k8 * 8 + (m >> 4)) * 128 + w + (r ^ k8);
}
// smem word index for B value (n in [0,128), k in [0,16)).
__device__ __forceinline__ int b_word(int n, int k) {
    int t = (n & 7) * 4 + (k & 3);
    int r = (k & 7) >> 2;
    int k8 = k >> 3;
    int w = (t * 2) ^ (((t >> 2) & 7) << 1) ^ (k8 << 1);
    return (k8 * 16 + (n >> 3)) * 64 + w + r;
}

// TN=false: C[m,n] = sum_k A[m*lda+k] * B[n*ldb+k]
// TN=true : C[m,n] = sum_k A[k*lda+m] * B[k*ldb+n]
template<bool TN>
__global__ __launch_bounds__(256) void gemm_tf32(
    const float* __restrict__ A, const float* __restrict__ B, float* __restrict__ C,
    int K, int lda, int ldb, int ldc,
    long long sA, long long sB, long long sC)
{
    __shared__ __align__(16) unsigned As[2][2048];
    __shared__ __align__(16) unsigned Bs[2][2048];
    A += (long long)blockIdx.z * sA;
    B += (long long)blockIdx.z * sB;
    C += (long long)blockIdx.z * sC;
    const int bm = blockIdx.y * 128;
    const int bn = blockIdx.x * 128;
    const int tid = threadIdx.x;
    const int lane = tid & 31;
    const int wm = ((tid >> 5) & 1) * 4;   // mtile offset (units of 16 rows)
    const int wn = ((tid >> 5) >> 1) * 4;  // ntile offset (units of 8 cols)

    float acc[4][4][4];
#pragma unroll
    for (int x = 0; x < 4; ++x)
#pragma unroll
        for (int y = 0; y < 4; ++y)
#pragma unroll
            for (int z = 0; z < 4; ++z) acc[x][y][z] = 0.0f;

    // staging thread mapping
    int r0, c0;
    if (!TN) { r0 = tid >> 2; c0 = (tid & 3) * 4; }   // r0 = row (m/n), c0 = k offset
    else     { r0 = tid & 15; c0 = (tid >> 4) * 8; }  // r0 = k, c0 = m/n base (8-wide)

    const int ntl = K / 16;
    float4 a0, a1, b0, b1;

    // ---- prefetch tile 0 ----
    if (!TN) {
        a0 = *(const float4*)(A + (long long)(bm + r0) * lda + c0);
        a1 = *(const float4*)(A + (long long)(bm + r0 + 64) * lda + c0);
        b0 = *(const float4*)(B + (long long)(bn + r0) * ldb + c0);
        b1 = *(const float4*)(B + (long long)(bn + r0 + 64) * ldb + c0);
    } else {
        a0 = *(const float4*)(A + (long long)r0 * lda + bm + c0);
        a1 = *(const float4*)(A + (long long)r0 * lda + bm + c0 + 4);
        b0 = *(const float4*)(B + (long long)r0 * ldb + bn + c0);
        b1 = *(const float4*)(B + (long long)r0 * ldb + bn + c0 + 4);
    }

    int buf = 0;
    {
        const float* av0 = (const float*)&a0;
        const float* av1 = (const float*)&a1;
        const float* bv0 = (const float*)&b0;
        const float* bv1 = (const float*)&b1;
        if (!TN) {
#pragma unroll
            for (int j = 0; j < 4; ++j) {
                As[0][a_word(r0,      c0 + j)] = f2tf(av0[j]);
                As[0][a_word(r0 + 64, c0 + j)] = f2tf(av1[j]);
                Bs[0][b_word(r0,      c0 + j)] = f2tf(bv0[j]);
                Bs[0][b_word(r0 + 64, c0 + j)] = f2tf(bv1[j]);
            }
        } else {
#pragma unroll
            for (int j = 0; j < 4; ++j) {
                As[0][a_word(c0 + j,     r0)] = f2tf(av0[j]);
                As[0][a_word(c0 + 4 + j, r0)] = f2tf(av1[j]);
                Bs[0][b_word(c0 + j,     r0)] = f2tf(bv0[j]);
                Bs[0][b_word(c0 + 4 + j, r0)] = f2tf(bv1[j]);
            }
        }
    }
    __syncthreads();

    for (int it = 0; it < ntl; ++it) {
        if (it + 1 < ntl) {
            const int k0 = (it + 1) * 16;
            if (!TN) {
                a0 = *(const float4*)(A + (long long)(bm + r0) * lda + k0 + c0);
                a1 = *(const float4*)(A + (long long)(bm + r0 + 64) * lda + k0 + c0);
                b0 = *(const float4*)(B + (long long)(bn + r0) * ldb + k0 + c0);
                b1 = *(const float4*)(B + (long long)(bn + r0 + 64) * ldb + k0 + c0);
            } else {
                a0 = *(const float4*)(A + (long long)(k0 + r0) * lda + bm + c0);
                a1 = *(const float4*)(A + (long long)(k0 + r0) * lda + bm + c0 + 4);
                b0 = *(const float4*)(B + (long long)(k0 + r0) * ldb + bn + c0);
                b1 = *(const float4*)(B + (long long)(k0 + r0) * ldb + bn + c0 + 4);
            }
        }
        const unsigned* Asb = As[buf];
        const unsigned* Bsb = Bs[buf];
#pragma unroll
        for (int k8 = 0; k8 < 2; ++k8) {
            unsigned af[4][4];
            unsigned bfm[4][2];
#pragma unroll
            for (int mt = 0; mt < 4; ++mt) {
                uint4 w = *(const uint4*)&Asb[(k8 * 8 + wm + mt) * 128 +
                                              ((lane * 4) ^ (((lane >> 2) & 7) << 2))];
                af[mt][0] = k8 ? w.y : w.x;
                af[mt][1] = k8 ? w.x : w.y;
                af[mt][2] = k8 ? w.w : w.z;
                af[mt][3] = k8 ? w.z : w.w;
            }
#pragma unroll
            for (int nt = 0; nt < 4; ++nt) {
                uint2 w = *(const uint2*)&Bsb[(k8 * 16 + wn + nt) * 64 +
                                              ((lane * 2) ^ (((lane >> 2) & 7) << 1) ^ (k8 << 1))];
                bfm[nt][0] = w.x;
                bfm[nt][1] = w.y;
            }
#pragma unroll
            for (int mt = 0; mt < 4; ++mt)
#pragma unroll
                for (int nt = 0; nt < 4; ++nt)
                    mma8(acc[mt][nt], af[mt], bfm[nt]);
        }
        if (it + 1 < ntl) {
            buf ^= 1;
            const float* av0 = (const float*)&a0;
            const float* av1 = (const float*)&a1;
            const float* bv0 = (const float*)&b0;
            const float* bv1 = (const float*)&b1;
            if (!TN) {
#pragma unroll
                for (int j = 0; j < 4; ++j) {
                    As[buf][a_word(r0,      c0 + j)] = f2tf(av0[j]);
                    As[buf][a_word(r0 + 64, c0 + j)] = f2tf(av1[j]);
                    Bs[buf][b_word(r0,      c0 + j)] = f2tf(bv0[j]);
                    Bs[buf][b_word(r0 + 64, c0 + j)] = f2tf(bv1[j]);
                }
            } else {
#pragma unroll
                for (int j = 0; j < 4; ++j) {
                    As[buf][a_word(c0 + j,     r0)] = f2tf(av0[j]);
                    As[buf][a_word(c0 + 4 + j, r0)] = f2tf(av1[j]);
                    Bs[buf][b_word(c0 + j,     r0)] = f2tf(bv0[j]);
                    Bs[buf][b_word(c0 + 4 + j, r0)] = f2tf(bv1[j]);
                }
            }
            __syncthreads();
        }
    }

    // ---- epilogue ----
    const int gid = lane >> 2;
    const int tig = lane & 3;
#pragma unroll
    for (int mt = 0; mt < 4; ++mt) {
        const long long row = bm + (wm + mt) * 16 + gid;
#pragma unroll
        for (int nt = 0; nt < 4; ++nt) {
            const int col = bn + (wn + nt) * 8 + tig * 2;
            *(float2*)(C + row * ldc + col) = make_float2(acc[mt][nt][0], acc[mt][nt][1]);
            *(float2*)(C + (row + 8) * ldc + col) = make_float2(acc[mt][nt][2], acc[mt][nt][3]);
        }
    }
}

// ============================================================
// 64x64 fp32 GEMM (N=64 cases: k_r, q_r) — FFMA2 mainloop
// ============================================================
#define SM_ 64
#define SK_ 16
__global__ __launch_bounds__(256) void gemm_nt64(
    const float* __restrict__ A, const float* __restrict__ B, float* __restrict__ C,
    int K, int lda, int ldb, int ldc,
    long long sA, long long sB, long long sC)
{
    __shared__ float As[SK_][SM_];
    __shared__ float Bs[SK_][SM_];
    A += (long long)blockIdx.z * sA;
    B += (long long)blockIdx.z * sB;
    C += (long long)blockIdx.z * sC;
    const int bm = blockIdx.y * SM_;
    const int bn = blockIdx.x * SM_;
    const int tid = threadIdx.x;
    const int tx = tid & 15;
    const int ty = tid >> 4;
    const int lrow = tid >> 2;
    const int lcol = (tid & 3) * 4;

    ull acc2[2][4] = {};

    for (int k0 = 0; k0 < K; k0 += SK_) {
        float4 a = *(const float4*)(A + (long long)(bm + lrow) * lda + k0 + lcol);
        float4 b = *(const float4*)(B + (long long)(bn + lrow) * ldb + k0 + lcol);
        __syncthreads();
        As[lcol + 0][lrow] = a.x; As[lcol + 1][lrow] = a.y;
        As[lcol + 2][lrow] = a.z; As[lcol + 3][lrow] = a.w;
        Bs[lcol + 0][lrow] = b.x; Bs[lcol + 1][lrow] = b.y;
        Bs[lcol + 2][lrow] = b.z; Bs[lcol + 3][lrow] = b.w;
        __syncthreads();
#pragma unroll
        for (int kk = 0; kk < SK_; ++kk) {
            float4 av = *(const float4*)(&As[kk][ty * 4]);
            float4 bv = *(const float4*)(&Bs[kk][tx * 4]);
            ull ap[2];
            ap[0] = ((const ull*)&av)[0];
            ap[1] = ((const ull*)&av)[1];
            ull bb[4];
            bb[0] = dup2(bv.x); bb[1] = dup2(bv.y);
            bb[2] = dup2(bv.z); bb[3] = dup2(bv.w);
#pragma unroll
            for (int p = 0; p < 2; ++p)
#pragma unroll
                for (int j = 0; j < 4; ++j)
                    ffma2(acc2[p][j], ap[p], bb[j]);
        }
    }

#pragma unroll
    for (int p = 0; p < 2; ++p) {
#pragma unroll
        for (int half = 0; half < 2; ++half) {
            const int crow = bm + ty * 4 + p * 2 + half;
            F2u v0, v1, v2, v3;
            v0.u = acc2[p][0]; v1.u = acc2[p][1];
            v2.u = acc2[p][2]; v3.u = acc2[p][3];
            float4 o = half ? make_float4(v0.f.y, v1.f.y, v2.f.y, v3.f.y)
                            : make_float4(v0.f.x, v1.f.x, v2.f.x, v3.f.x);
            *(float4*)(C + (long long)crow * ldc + bn + tx * 4) = o;
        }
    }
}

// ============================================================
// Elementwise kernels
// ============================================================
__global__ void rope_q_kernel(float* __restrict__ q, const float* __restrict__ freqs)
{
    int idx = blockIdx.x * blockDim.x + threadIdx.x;   // NH*T*32
    int i = idx & 31;
    int t = (idx >> 5) & (T - 1);
    int n = idx >> 16;
    float ang = freqs[t * (DRH / 2) + i];
    float c, s;
    __sincosf(ang, &s, &c);
    float* base = q + ((size_t)(n * T + t)) * QKD + DH;
    float re = base[i], im = base[i + 32];
    base[i]      = re * c - im * s;
    base[i + 32] = re * s + im * c;
}

__global__ void rope_k_bcast_kernel(const float* __restrict__ kr, float* __restrict__ kbuf,
                                    const float* __restrict__ freqs)
{
    int idx = blockIdx.x * blockDim.x + threadIdx.x;   // T*32
    int i = idx & 31;
    int t = idx >> 5;
    float ang = freqs[t * (DRH / 2) + i];
    float c, s;
    __sincosf(ang, &s, &c);
    float re = kr[t * DRH + i], im = kr[t * DRH + 32 + i];
    const float inv_nh = 1.0f / (float)NH;
    float rr = (re * c - im * s) * inv_nh;
    float ri = (re * s + im * c) * inv_nh;
#pragma unroll
    for (int n = 0; n < NH; ++n) {
        float* b = kbuf + ((size_t)(n * T + t)) * QKD + DH;
        b[i]      = rr;
        b[i + 32] = ri;
    }
}

__global__ void wo_transpose_kernel(const float* __restrict__ wo, float* __restrict__ wt)
{
    int idx = blockIdx.x * blockDim.x + threadIdx.x;   // D * NH * DH
    int j = idx & (NH * DH - 1);
    int d = idx >> 11;
    int n = j >> 7;
    int e = j & (DH - 1);
    wt[idx] = wo[(size_t)d * (DH * NH) + e * NH + n];
}

__global__ __launch_bounds__(256) void softmax_kernel(
    float* __restrict__ logits, const float* __restrict__ mask, float scale)
{
    const int t = blockIdx.x;
    const int n = blockIdx.y;
    float* __restrict__ row = logits + ((size_t)n * T + t) * T;
    const float* __restrict__ mrow = mask + (size_t)t * T;
    const int tid = threadIdx.x;

    float v[8];
    float mx = -1e30f;
#pragma unroll
    for (int j = 0; j < 8; ++j) {
        int l = tid + j * 256;
        v[j] = fmaf(row[l], scale, mrow[l]);
        mx = fmaxf(mx, v[j]);
    }
    __shared__ float redm[8], reds[8];
#pragma unroll
    for (int o = 16; o; o >>= 1) mx = fmaxf(mx, __shfl_xor_sync(0xffffffffu, mx, o));
    if ((tid & 31) == 0) redm[tid >> 5] = mx;
    __syncthreads();
    mx = redm[0];
#pragma unroll
    for (int w = 1; w < 8; ++w) mx = fmaxf(mx, redm[w]);

    float sum = 0.0f;
#pragma unroll
    for (int j = 0; j < 8; ++j) {
        v[j] = __expf(v[j] - mx);
        sum += v[j];
    }
#pragma unroll
    for (int o = 16; o; o >>= 1) sum += __shfl_xor_sync(0xffffffffu, sum, o);
    if ((tid & 31) == 0) reds[tid >> 5] = sum;
    __syncthreads();
    sum = reds[0];
#pragma unroll
    for (int w = 1; w < 8; ++w) sum += reds[w];

    float inv = 1.0f / sum;
#pragma unroll
    for (int j = 0; j < 8; ++j)
        row[tid + j * 256] = v[j] * inv;
}

// ============================================================
// Launch
// ============================================================
extern "C" void kernel_launch(void* const* d_in, const int* in_sizes, int n_in,
                              void* d_out, int out_size)
{
    const float* h     = (const float*)d_in[0];
    const float* freqs = (const float*)d_in[1];
    const float* mask  = (const float*)d_in[2];
    const float* w_dkv = (const float*)d_in[3];
    const float* w_uk  = (const float*)d_in[4];
    const float* w_uv  = (const float*)d_in[5];
    const float* w_dq  = (const float*)d_in[6];
    const float* w_uq  = (const float*)d_in[7];
    const float* w_qr  = (const float*)d_in[8];
    const float* w_kr  = (const float*)d_in[9];
    const float* w_o   = (const float*)d_in[10];
    float* out = (float*)d_out;
    (void)in_sizes; (void)n_in; (void)out_size;

    float *ckv, *cq, *q, *k, *v, *kr, *logits, *attn, *wot;
    cudaGetSymbolAddress((void**)&ckv,    g_ckv);
    cudaGetSymbolAddress((void**)&cq,     g_cq);
    cudaGetSymbolAddress((void**)&q,      g_q);
    cudaGetSymbolAddress((void**)&k,      g_k);
    cudaGetSymbolAddress((void**)&v,      g_v);
    cudaGetSymbolAddress((void**)&kr,     g_kr);
    cudaGetSymbolAddress((void**)&logits, g_logits);
    cudaGetSymbolAddress((void**)&attn,   g_attn);
    cudaGetSymbolAddress((void**)&wot,    g_wot);

    const dim3 blk(256);
    const long long sQ = (long long)T * QKD;

    // Latents: c_kv, c_q = h @ W^T   (M=2048, N=512, K=2048)
    gemm_tf32<false><<<dim3(DC / 128, T / 128, 1), blk>>>(h, w_dkv, ckv, D, D, D, DC, 0, 0, 0);
    gemm_tf32<false><<<dim3(DC / 128, T / 128, 1), blk>>>(h, w_dq,  cq,  D, D, D, DC, 0, 0, 0);
    // k_r (pre-rope): N=64, fp32
    gemm_nt64<<<dim3(1, T / SM_, 1), blk>>>(h, w_kr, kr, D, D, D, DRH, 0, 0, 0);

    // Per-head up-projections (N=128, K=512, batched over heads)
    gemm_tf32<false><<<dim3(1, T / 128, NH), blk>>>(ckv, w_uk, k, DC, DC, NH * DC, QKD, 0, DC, sQ);
    gemm_tf32<false><<<dim3(1, T / 128, NH), blk>>>(ckv, w_uv, v, DC, DC, NH * DC, DH,  0, DC, (long long)T * DH);
    gemm_tf32<false><<<dim3(1, T / 128, NH), blk>>>(cq,  w_uq, q, DC, DC, NH * DC, QKD, 0, DC, sQ);
    // q_r: N=64, fp32
    gemm_nt64<<<dim3(1, T / SM_, NH), blk>>>(cq, w_qr, q + DH, DC, DC, NH * DC, QKD, 0, DC, sQ);

    // Rope
    rope_q_kernel<<<(NH * T * 32) / 256, 256>>>(q, freqs);
    rope_k_bcast_kernel<<<(T * 32) / 256, 256>>>(kr, k, freqs);

    // logits[n,t,l] = q . k   (M=N=2048, K=192)
    gemm_tf32<false><<<dim3(T / 128, T / 128, NH), blk>>>(q, k, logits, QKD, QKD, QKD, T, sQ, sQ, (long long)T * T);

    // softmax over l with mask, scale = 1/sqrt(192)
    softmax_kernel<<<dim3(T, NH), 256>>>(logits, mask, 0.07216878364870323f);

    // out[n,l,e] = sum_t S[n,t,l] v[n,t,e]   (TN: contract over rows)
    gemm_tf32<true><<<dim3(1, T / 128, NH), blk>>>(logits, v, attn, T, T, DH, NH * DH,
                                                   (long long)T * T, (long long)T * DH, DH);

    // w_o permute then final projection (M=2048, N=2048, K=2048)
    wo_transpose_kernel<<<(D * NH * DH) / 256, 256>>>(w_o, wot);
    gemm_tf32<false><<<dim3(D / 128, T / 128, 1), blk>>>(attn, wot, out, NH * DH, NH * DH, NH * DH, D, 0, 0, 0);
}